// round 12
// baseline (speedup 1.0000x reference)
#include <cuda_runtime.h>
#include <cuda_fp16.h>

#define NN 100000
#define EMAX 1600000
#define EPS 1e-5f
#define NB ((NN + 1023) >> 10)     // 98 scan blocks
#define GSTRIDE 88                 // smem row stride (uints): conflict-free LDS.64/STS.128

typedef unsigned int uint;

// ---- scratch (device globals) ----
// interleaved fp16 layout: per row 128 k-vals = 8 groups x 8 uints (half2 each)
__device__ __align__(256) uint   g_y1l[NN * 64];   // x@(W1l*g)^T, fp16 interleaved
__device__ __align__(256) uint   g_hx [NN * 64];   // x@(W1r*g)^T, fp16 interleaved
__device__ __align__(256) uint   g_h  [NN * 64];   // layer-1 out, fp16 interleaved
__device__ __align__(256) __half g_y2l[NN * 64];   // h@W2l^T, fp16 plain
__device__ __align__(256) float  g_y2r[NN * 64];   // h@W2r^T, fp32 plain
__device__ __align__(16) float g_biasI[128];       // BN-folded bias, interleaved-half order
__device__ int g_cnt_i[NN];
__device__ int g_off[NN + 1];
__device__ int g_cur[NN];
__device__ int g_bsum[NB];
__device__ int g_ssrc[EMAX];

// ---- helpers ----
__device__ __forceinline__ uint h2u(float lo, float hi) {
    __half2 h = __floats2half2_rn(lo, hi);
    return *(uint*)&h;
}
__device__ __forceinline__ void mma16(float* d, const uint* a, const uint* b) {
    asm("mma.sync.aligned.m16n8k16.row.col.f32.f16.f16.f32 "
        "{%0,%1,%2,%3}, {%4,%5,%6,%7}, {%8,%9}, {%0,%1,%2,%3};"
        : "+f"(d[0]), "+f"(d[1]), "+f"(d[2]), "+f"(d[3])
        : "r"(a[0]), "r"(a[1]), "r"(a[2]), "r"(a[3]), "r"(b[0]), "r"(b[1]));
}
__device__ __forceinline__ void acc8(float* a, uint4 v) {
    float2 f;
    f = __half22float2(*(__half2*)&v.x); a[0] += f.x; a[1] += f.y;
    f = __half22float2(*(__half2*)&v.y); a[2] += f.x; a[3] += f.y;
    f = __half22float2(*(__half2*)&v.z); a[4] += f.x; a[5] += f.y;
    f = __half22float2(*(__half2*)&v.w); a[6] += f.x; a[7] += f.y;
}
__device__ __forceinline__ void acc4(float* a, uint2 v) {
    float2 f;
    f = __half22float2(*(__half2*)&v.x); a[0] += f.x; a[1] += f.y;
    f = __half22float2(*(__half2*)&v.y); a[2] += f.x; a[3] += f.y;
}

// ===========================================================================
// zero counters + precompute interleaved BN-folded bias
// ===========================================================================
__global__ void zerocnt_kernel(const float* __restrict__ b1l,
                               const float* __restrict__ gamma,
                               const float* __restrict__ beta,
                               const float* __restrict__ rmean,
                               const float* __restrict__ rvar) {
    int i = blockIdx.x * blockDim.x + threadIdx.x;
    if (i < NN) g_cnt_i[i] = 0;
    if (blockIdx.x == 0 && threadIdx.x < 128) {
        int hidx = threadIdx.x;
        int uidx = hidx >> 1, hh = hidx & 1;
        int gi = uidx >> 3, j = uidx & 7;
        int t4 = (j >> 1) + ((j & 1) << 2);
        int col = gi * 16 + t4 * 2 + hh;
        float g = gamma[col] * rsqrtf(rvar[col] + EPS);
        g_biasI[hidx] = (b1l[col] - rmean[col]) * g + beta[col];
    }
}

// ===========================================================================
// CSR build
// ===========================================================================
__global__ void hist4_kernel(const int4* __restrict__ dst4, int E4,
                             const int* __restrict__ dst, int E) {
    int i = blockIdx.x * blockDim.x + threadIdx.x;
    if (i < E4) {
        int4 d = __ldg(dst4 + i);
        atomicAdd(&g_cnt_i[d.x], 1);
        atomicAdd(&g_cnt_i[d.y], 1);
        atomicAdd(&g_cnt_i[d.z], 1);
        atomicAdd(&g_cnt_i[d.w], 1);
    }
    if (i == 0)
        for (int e = E4 * 4; e < E; e++) atomicAdd(&g_cnt_i[__ldg(dst + e)], 1);
}

__global__ void hist_kernel(const int* __restrict__ dst, int E) {
    int e = blockIdx.x * blockDim.x + threadIdx.x;
    if (e < E) atomicAdd(&g_cnt_i[dst[e]], 1);
}

__global__ void scan1_kernel() {
    __shared__ int sm[1024];
    int tid = threadIdx.x;
    int i = blockIdx.x * 1024 + tid;
    int v = (i < NN) ? g_cnt_i[i] : 0;
    sm[tid] = v;
    __syncthreads();
    for (int off = 1; off < 1024; off <<= 1) {
        int t = (tid >= off) ? sm[tid - off] : 0;
        __syncthreads();
        sm[tid] += t;
        __syncthreads();
    }
    if (i < NN) g_off[i] = sm[tid] - v;
    if (tid == 1023) g_bsum[blockIdx.x] = sm[1023];
}

__global__ void scan23_kernel(int E) {
    __shared__ int sm[128];
    int tid = threadIdx.x;
    if (tid < 128) sm[tid] = (tid < NB) ? g_bsum[tid] : 0;
    __syncthreads();
    for (int off = 1; off < 128; off <<= 1) {
        int t = (tid < 128 && tid >= off) ? sm[tid - off] : 0;
        __syncthreads();
        if (tid < 128) sm[tid] += t;
        __syncthreads();
    }
    int i = blockIdx.x * blockDim.x + tid;
    if (i < NN) {
        int b = i >> 10;
        int o = g_off[i] + (b ? sm[b - 1] : 0);
        g_off[i] = o;
        g_cur[i] = o;
    }
    if (i == 0) g_off[NN] = E;
}

__global__ void fill4_kernel(const int4* __restrict__ src4, const int4* __restrict__ dst4,
                             int E4, const int* __restrict__ src,
                             const int* __restrict__ dst, int E) {
    int i = blockIdx.x * blockDim.x + threadIdx.x;
    if (i < E4) {
        int4 s = __ldg(src4 + i);
        int4 d = __ldg(dst4 + i);
        g_ssrc[atomicAdd(&g_cur[d.x], 1)] = s.x;
        g_ssrc[atomicAdd(&g_cur[d.y], 1)] = s.y;
        g_ssrc[atomicAdd(&g_cur[d.z], 1)] = s.z;
        g_ssrc[atomicAdd(&g_cur[d.w], 1)] = s.w;
    }
    if (i == 0)
        for (int e = E4 * 4; e < E; e++)
            g_ssrc[atomicAdd(&g_cur[__ldg(dst + e)], 1)] = __ldg(src + e);
}

__global__ void fill_kernel(const int* __restrict__ src,
                            const int* __restrict__ dst, int E) {
    int e = blockIdx.x * blockDim.x + threadIdx.x;
    if (e >= E) return;
    int p = atomicAdd(&g_cur[dst[e]], 1);
    g_ssrc[p] = src[e];
}

// ===========================================================================
// agg1: warp per dst; HALF-warp per edge (16 lanes x uint4 = 256B row).
// Two edges in flight per warp step; shfl_xor(16) merges the halves.
// Epilogue: mean + hx + interleaved bias, ReLU -> g_h (interleaved fp16).
// ===========================================================================
__global__ void __launch_bounds__(256) agg1_kernel() {
    int w = (blockIdx.x * 256 + threadIdx.x) >> 5;
    if (w >= NN) return;
    int lane = threadIdx.x & 31;
    int half = lane >> 4, sl = lane & 15;
    int beg = g_off[w], end = g_off[w + 1];
    float a[8] = {0.f, 0.f, 0.f, 0.f, 0.f, 0.f, 0.f, 0.f};
    const uint4* yl = (const uint4*)g_y1l;       // 16 uint4 per row
    int e = beg + half;
    for (; e + 2 < end; e += 4) {                // e and e+2 both valid
        int s0 = __ldg(g_ssrc + e);
        int s1 = __ldg(g_ssrc + e + 2);
        uint4 v0 = __ldg(yl + s0 * 16 + sl);
        uint4 v1 = __ldg(yl + s1 * 16 + sl);
        acc8(a, v0);
        acc8(a, v1);
    }
    if (e < end) {
        int s0 = __ldg(g_ssrc + e);
        uint4 v0 = __ldg(yl + s0 * 16 + sl);
        acc8(a, v0);
    }
    #pragma unroll
    for (int i = 0; i < 8; i++) a[i] += __shfl_xor_sync(0xffffffffu, a[i], 16);
    if (half == 0) {
        float inv = 1.f / (float)max(end - beg, 1);
        uint4 hx = ((const uint4*)g_hx)[w * 16 + sl];
        float4 b0 = *(const float4*)(g_biasI + 8 * sl);
        float4 b1 = *(const float4*)(g_biasI + 8 * sl + 4);
        float2 h0 = __half22float2(*(__half2*)&hx.x);
        float2 h1 = __half22float2(*(__half2*)&hx.y);
        float2 h2 = __half22float2(*(__half2*)&hx.z);
        float2 h3 = __half22float2(*(__half2*)&hx.w);
        uint4 o;
        o.x = h2u(fmaxf(a[0] * inv + h0.x + b0.x, 0.f),
                  fmaxf(a[1] * inv + h0.y + b0.y, 0.f));
        o.y = h2u(fmaxf(a[2] * inv + h1.x + b0.z, 0.f),
                  fmaxf(a[3] * inv + h1.y + b0.w, 0.f));
        o.z = h2u(fmaxf(a[4] * inv + h2.x + b1.x, 0.f),
                  fmaxf(a[5] * inv + h2.y + b1.y, 0.f));
        o.w = h2u(fmaxf(a[6] * inv + h3.x + b1.z, 0.f),
                  fmaxf(a[7] * inv + h3.y + b1.w, 0.f));
        ((uint4*)g_h)[w * 16 + sl] = o;
    }
}

// ===========================================================================
// agg2 + epilogue: warp per dst; HALF-warp per edge (16 lanes x uint2 = 128B).
// out[d] = mean_agg(y2l fp16) + b2l + y2r[d]
// ===========================================================================
__global__ void __launch_bounds__(256) agg2_kernel(const float* __restrict__ b2l,
                                                   float* __restrict__ out) {
    int w = (blockIdx.x * 256 + threadIdx.x) >> 5;
    if (w >= NN) return;
    int lane = threadIdx.x & 31;
    int half = lane >> 4, sl = lane & 15;
    int beg = g_off[w], end = g_off[w + 1];
    float a[4] = {0.f, 0.f, 0.f, 0.f};
    const uint2* yl = (const uint2*)g_y2l;       // 16 uint2 per row
    int e = beg + half;
    for (; e + 2 < end; e += 4) {
        int s0 = __ldg(g_ssrc + e);
        int s1 = __ldg(g_ssrc + e + 2);
        uint2 v0 = __ldg(yl + s0 * 16 + sl);
        uint2 v1 = __ldg(yl + s1 * 16 + sl);
        acc4(a, v0);
        acc4(a, v1);
    }
    if (e < end) {
        int s0 = __ldg(g_ssrc + e);
        uint2 v0 = __ldg(yl + s0 * 16 + sl);
        acc4(a, v0);
    }
    #pragma unroll
    for (int i = 0; i < 4; i++) a[i] += __shfl_xor_sync(0xffffffffu, a[i], 16);
    if (half == 0) {
        float inv = 1.f / (float)max(end - beg, 1);
        int j = sl * 4;
        float4 yr = *(const float4*)(g_y2r + (long long)w * 64 + j);
        float4 bb = *(const float4*)(b2l + j);
        float4 o = make_float4(a[0] * inv + bb.x + yr.x,
                               a[1] * inv + bb.y + yr.y,
                               a[2] * inv + bb.z + yr.z,
                               a[3] * inv + bb.w + yr.w);
        *(float4*)(out + (long long)w * 64 + j) = o;
    }
}

// ===========================================================================
// fp16 HMMA GEMMs. Block tile 128x128, 8 warps, warp tile 32x64, k-chunk 128.
// ===========================================================================
#define TILE_U (128 * GSTRIDE)
#define GEMMW_SMEM ((2 * TILE_U + 128) * 4)
#define GEMMA_SMEM ((2 * TILE_U) * 4)

// copy of a pre-interleaved fp16 tile (row-major, 64 uints/row)
__device__ __forceinline__ void copy_tile(uint* S, const uint* __restrict__ src,
                                          int g0, int tid) {
    #pragma unroll
    for (int it = 0; it < 8; it++) {
        int u = it * 256 + tid;
        int r = u >> 4, j = u & 15;
        int grow = g0 + r;
        uint4 v = make_uint4(0u, 0u, 0u, 0u);
        if (grow < NN) v = __ldg((const uint4*)(src + grow * 64) + j);
        *(uint4*)(S + r * GSTRIDE + j * 4) = v;
    }
}

// fp32 x tile -> interleaved fp16 smem (fused convx)
__device__ __forceinline__ void convx_tile(uint* S, const float* __restrict__ x,
                                           int g0, int tid) {
    #pragma unroll
    for (int it = 0; it < 4; it++) {
        int u = it * 256 + tid;            // 1024 items: (r:7)(g:3)
        int r = u >> 3, g = u & 7;
        int grow = g0 + r;
        float4 a = make_float4(0.f, 0.f, 0.f, 0.f), b = a, c = a, d = a;
        if (grow < NN) {
            const float4* p = (const float4*)(x + (long long)grow * 128 + g * 16);
            a = __ldg(p); b = __ldg(p + 1); c = __ldg(p + 2); d = __ldg(p + 3);
        }
        uint4 o0 = make_uint4(h2u(a.x, a.y), h2u(c.x, c.y), h2u(a.z, a.w), h2u(c.z, c.w));
        uint4 o1 = make_uint4(h2u(b.x, b.y), h2u(d.x, d.y), h2u(b.z, b.w), h2u(d.z, d.w));
        uint4* q = (uint4*)(S + r * GSTRIDE + g * 8);
        q[0] = o0; q[1] = o1;
    }
}

__device__ __forceinline__ void convw_tile(uint* S, const float* __restrict__ W0,
                                           const float* gp, int tid) {
    #pragma unroll
    for (int it = 0; it < 8; it++) {
        int u = it * 256 + tid;
        int n = u >> 4, g = (u >> 1) & 7, h = u & 1;
        const float* p = W0 + n * 128 + g * 16 + 4 * h;
        float4 A = __ldg((const float4*)p);
        float4 B = __ldg((const float4*)(p + 8));
        float s = gp ? gp[n] : 1.f;
        uint4 o = make_uint4(h2u(A.x * s, A.y * s), h2u(B.x * s, B.y * s),
                             h2u(A.z * s, A.w * s), h2u(B.z * s, B.w * s));
        *(uint4*)(S + n * GSTRIDE + g * 8 + 4 * h) = o;
    }
}

struct FAcc { float a[2][8][4]; };

__device__ __forceinline__ void acc_zero(FAcc& acc) {
    #pragma unroll
    for (int i = 0; i < 2; i++)
        #pragma unroll
        for (int j = 0; j < 8; j++)
            #pragma unroll
            for (int q = 0; q < 4; q++) acc.a[i][j][q] = 0.f;
}

__device__ __forceinline__ void mainloop_h(const uint* As, const uint* Ws,
                                           int warpM, int warpN, int fr, int cc,
                                           FAcc& acc) {
    const uint* Ab = As + (warpM * 32 + fr) * GSTRIDE + 2 * cc;
    const uint* Bb = Ws + (warpN * 64 + fr) * GSTRIDE + 2 * cc;
    #pragma unroll
    for (int g = 0; g < 8; g++) {
        uint a[2][4];
        #pragma unroll
        for (int mt = 0; mt < 2; mt++) {
            uint2 p0 = *(const uint2*)(Ab + (mt * 16) * GSTRIDE + g * 8);
            uint2 p1 = *(const uint2*)(Ab + (mt * 16 + 8) * GSTRIDE + g * 8);
            a[mt][0] = p0.x; a[mt][1] = p1.x; a[mt][2] = p0.y; a[mt][3] = p1.y;
        }
        #pragma unroll
        for (int nt = 0; nt < 8; nt++) {
            uint2 q = *(const uint2*)(Bb + (nt * 8) * GSTRIDE + g * 8);
            uint b[2] = {q.x, q.y};
            mma16(acc.a[0][nt], a[0], b);
            mma16(acc.a[1][nt], a[1], b);
        }
    }
}

// gemmW: blockIdx.y==0 -> g_y1l = x@(W1l*gp)^T ; ==1 -> g_hx = x@(W1r*gp)^T
// x converted inline (no staging buffer); output interleaved fp16
__global__ void __launch_bounds__(256, 2) gemmW_kernel(
    const float* __restrict__ x,
    const float* __restrict__ W1l, const float* __restrict__ W1r,
    const float* __restrict__ gamma, const float* __restrict__ rvar)
{
    extern __shared__ uint smu[];
    uint* As = smu;
    uint* Ws = smu + TILE_U;
    float* gp = (float*)(smu + 2 * TILE_U);

    int tid = threadIdx.x;
    int g0 = blockIdx.x * 128;
    int which = blockIdx.y;
    const float* W = which ? W1r : W1l;
    uint* outp = which ? g_hx : g_y1l;

    if (tid < 128) gp[tid] = gamma[tid] * rsqrtf(rvar[tid] + EPS);
    __syncthreads();

    convw_tile(Ws, W, gp, tid);
    convx_tile(As, x, g0, tid);
    __syncthreads();

    int lane = tid & 31, wid = tid >> 5;
    int warpM = wid >> 1, warpN = wid & 1;
    int fr = lane >> 2, cc = lane & 3;

    FAcc acc;
    acc_zero(acc);
    mainloop_h(As, Ws, warpM, warpN, fr, cc, acc);

    #pragma unroll
    for (int mt = 0; mt < 2; mt++) {
        int r0 = g0 + warpM * 32 + mt * 16 + fr;
        #pragma unroll
        for (int nt = 0; nt < 8; nt++) {
            int col = warpN * 64 + nt * 8 + 2 * cc;
            int t4 = (col & 15) >> 1;
            int j = (t4 < 4) ? 2 * t4 : 2 * (t4 - 4) + 1;
            int uidx = (col >> 4) * 8 + j;
            if (r0 < NN)
                outp[r0 * 64 + uidx] = h2u(acc.a[mt][nt][0], acc.a[mt][nt][1]);
            if (r0 + 8 < NN)
                outp[(r0 + 8) * 64 + uidx] = h2u(acc.a[mt][nt][2], acc.a[mt][nt][3]);
        }
    }
}

// gemmA: y2l = h@W2l^T (fp16), y2r = h@W2r^T (fp32)
__global__ void __launch_bounds__(256, 2) gemmA_kernel(
    const float* __restrict__ W2l, const float* __restrict__ W2r)
{
    extern __shared__ uint smu[];
    uint* As = smu;
    uint* Ws = smu + TILE_U;

    int tid = threadIdx.x;
    int g0 = blockIdx.x * 128;

    // W2 tile: n 0..63 -> W2l, 64..127 -> W2r
    #pragma unroll
    for (int it = 0; it < 8; it++) {
        int u = it * 256 + tid;
        int n = u >> 4, g = (u >> 1) & 7, h = u & 1;
        const float* Wsrc = (n < 64) ? (W2l + n * 128) : (W2r + (n - 64) * 128);
        const float* p = Wsrc + g * 16 + 4 * h;
        float4 A = __ldg((const float4*)p);
        float4 B = __ldg((const float4*)(p + 8));
        uint4 o = make_uint4(h2u(A.x, A.y), h2u(B.x, B.y),
                             h2u(A.z, A.w), h2u(B.z, B.w));
        *(uint4*)(Ws + n * GSTRIDE + g * 8 + 4 * h) = o;
    }
    copy_tile(As, g_h, g0, tid);
    __syncthreads();

    int lane = tid & 31, wid = tid >> 5;
    int warpM = wid >> 1, warpN = wid & 1;
    int fr = lane >> 2, cc = lane & 3;

    FAcc acc;
    acc_zero(acc);
    mainloop_h(As, Ws, warpM, warpN, fr, cc, acc);

    #pragma unroll
    for (int mt = 0; mt < 2; mt++) {
        int r0 = g0 + warpM * 32 + mt * 16 + fr;
        #pragma unroll
        for (int nt = 0; nt < 8; nt++) {
            int colL = nt * 8 + 2 * cc;
            if (warpN == 0) {
                if (r0 < NN)
                    *(__half2*)(g_y2l + (long long)r0 * 64 + colL) =
                        __floats2half2_rn(acc.a[mt][nt][0], acc.a[mt][nt][1]);
                if (r0 + 8 < NN)
                    *(__half2*)(g_y2l + (long long)(r0 + 8) * 64 + colL) =
                        __floats2half2_rn(acc.a[mt][nt][2], acc.a[mt][nt][3]);
            } else {
                if (r0 < NN)
                    *(float2*)(g_y2r + (long long)r0 * 64 + colL) =
                        make_float2(acc.a[mt][nt][0], acc.a[mt][nt][1]);
                if (r0 + 8 < NN)
                    *(float2*)(g_y2r + (long long)(r0 + 8) * 64 + colL) =
                        make_float2(acc.a[mt][nt][2], acc.a[mt][nt][3]);
            }
        }
    }
}

// ===========================================================================
extern "C" void kernel_launch(void* const* d_in, const int* in_sizes, int n_in,
                              void* d_out, int out_size) {
    const float* x     = (const float*)d_in[0];
    const int*   ei    = (const int*)d_in[1];     // int32 (JAX x64 disabled)
    const float* W1l   = (const float*)d_in[2];
    const float* b1l   = (const float*)d_in[3];
    const float* W1r   = (const float*)d_in[4];
    const float* gamma = (const float*)d_in[5];
    const float* beta  = (const float*)d_in[6];
    const float* rmean = (const float*)d_in[7];
    const float* rvar  = (const float*)d_in[8];
    const float* W2l   = (const float*)d_in[9];
    const float* b2l   = (const float*)d_in[10];
    const float* W2r   = (const float*)d_in[11];
    float* out = (float*)d_out;

    int E = in_sizes[1] / 2;
    if (E > EMAX) E = EMAX;
    const int* src = ei;
    const int* dst = ei + E;

    cudaFuncSetAttribute(gemmW_kernel, cudaFuncAttributeMaxDynamicSharedMemorySize, GEMMW_SMEM);
    cudaFuncSetAttribute(gemmA_kernel, cudaFuncAttributeMaxDynamicSharedMemorySize, GEMMA_SMEM);

    int nBlk  = (NN + 255) / 256;         // 391
    int wBlk  = (NN * 32 + 255) / 256;    // 12500
    int gBlk  = (NN + 127) / 128;         // 782

    // side stream + events (same pattern as R8-R11 — verified capture-safe)
    cudaStream_t s2;
    cudaStreamCreateWithFlags(&s2, cudaStreamNonBlocking);
    cudaEvent_t e0, e2;
    cudaEventCreateWithFlags(&e0, cudaEventDisableTiming);
    cudaEventCreateWithFlags(&e2, cudaEventDisableTiming);

    cudaEventRecord(e0, 0);
    cudaStreamWaitEvent(s2, e0, 0);

    // stream B: both W1 halves of x (independent of graph build; x converted inline)
    gemmW_kernel<<<dim3(gBlk, 2), 256, GEMMW_SMEM, s2>>>(x, W1l, W1r, gamma, rvar);
    cudaEventRecord(e2, s2);

    // stream A (capture stream): CSR build
    zerocnt_kernel<<<nBlk, 256>>>(b1l, gamma, beta, rmean, rvar);
    if ((E & 3) == 0) {
        int E4 = E >> 2;
        int e4Blk = (E4 + 255) / 256;
        hist4_kernel<<<e4Blk, 256>>>((const int4*)dst, E4, dst, E);
        scan1_kernel<<<NB, 1024>>>();
        scan23_kernel<<<nBlk, 256>>>(E);
        fill4_kernel<<<e4Blk, 256>>>((const int4*)src, (const int4*)dst, E4, src, dst, E);
    } else {
        int eBlk = (E + 255) / 256;
        hist_kernel<<<eBlk, 256>>>(dst, E);
        scan1_kernel<<<NB, 1024>>>();
        scan23_kernel<<<nBlk, 256>>>(E);
        fill_kernel<<<eBlk, 256>>>(src, dst, E);
    }

    cudaStreamWaitEvent(0, e2, 0);        // agg1 needs g_y1l + g_hx
    agg1_kernel<<<wBlk, 256>>>();
    gemmA_kernel<<<gBlk, 256, GEMMA_SMEM>>>(W2l, W2r);
    agg2_kernel<<<wBlk, 256>>>(b2l, out);
}

// round 15
// speedup vs baseline: 1.0285x; 1.0285x over previous
#include <cuda_runtime.h>
#include <cuda_fp16.h>

#define NN 100000
#define EMAX 1600000
#define EPS 1e-5f
#define NB ((NN + 1023) >> 10)     // 98 scan blocks
#define GSTRIDE 88                 // smem row stride (uints): conflict-free LDS.64/STS.128

typedef unsigned int uint;

// ---- scratch (device globals) ----
// interleaved fp16 layout: per row 128 k-values = 8 groups x 8 uints (half2 each),
// group order [k01,k89,k23,k10-11,k45,k12-13,k67,k14-15]
__device__ __align__(256) uint   g_xh [NN * 64];   // x, fp16 interleaved
__device__ __align__(256) uint   g_ag1[NN * 64];   // mean-agg(x), fp16 interleaved
__device__ __align__(256) uint   g_h  [NN * 64];   // layer-1 out, fp16 interleaved
__device__ __align__(256) __half g_y2l[NN * 64];   // h@W2l^T, fp16 plain
__device__ __align__(256) float  g_y2r[NN * 64];   // h@W2r^T, fp32 plain
__device__ int g_cnt_i[NN];
__device__ int g_off[NN + 1];
__device__ int g_bsum[NB];
__device__ int g_rank[EMAX];    // edge's rank within its dst bucket (from hist)
__device__ int g_ssrc[EMAX];

// ---- helpers ----
__device__ __forceinline__ uint h2u(float lo, float hi) {
    __half2 h = __floats2half2_rn(lo, hi);
    return *(uint*)&h;
}
__device__ __forceinline__ void mma16(float* d, const uint* a, const uint* b) {
    asm("mma.sync.aligned.m16n8k16.row.col.f32.f16.f16.f32 "
        "{%0,%1,%2,%3}, {%4,%5,%6,%7}, {%8,%9}, {%0,%1,%2,%3};"
        : "+f"(d[0]), "+f"(d[1]), "+f"(d[2]), "+f"(d[3])
        : "r"(a[0]), "r"(a[1]), "r"(a[2]), "r"(a[3]), "r"(b[0]), "r"(b[1]));
}

// ===========================================================================
// fused: zero hist counters + convert x -> interleaved fp16
// ===========================================================================
__global__ void zeroconv_kernel(const float* __restrict__ x) {
    int u = blockIdx.x * 256 + threadIdx.x;
    if (u < NN) g_cnt_i[u] = 0;
    if (u >= NN * 8) return;
    int row = u >> 3, g = u & 7;
    const float4* p = (const float4*)(x + row * 128 + g * 16);
    float4 a = __ldg(p);        // k0-3
    float4 b = __ldg(p + 1);    // k4-7
    float4 c = __ldg(p + 2);    // k8-11
    float4 d = __ldg(p + 3);    // k12-15
    uint4 o0 = make_uint4(h2u(a.x, a.y), h2u(c.x, c.y), h2u(a.z, a.w), h2u(c.z, c.w));
    uint4 o1 = make_uint4(h2u(b.x, b.y), h2u(d.x, d.y), h2u(b.z, b.w), h2u(d.z, d.w));
    uint4* q = (uint4*)(g_xh + row * 64 + g * 8);
    q[0] = o0; q[1] = o1;
}

// ===========================================================================
// CSR build — hist records each edge's bucket rank; fill is atomic-free.
// ===========================================================================
__global__ void hist_kernel(const int* __restrict__ dst, int E) {
    int e = blockIdx.x * blockDim.x + threadIdx.x;
    if (e < E) g_rank[e] = atomicAdd(&g_cnt_i[dst[e]], 1);
}

__global__ void scan1_kernel() {
    __shared__ int sm[1024];
    int tid = threadIdx.x;
    int i = blockIdx.x * 1024 + tid;
    int v = (i < NN) ? g_cnt_i[i] : 0;
    sm[tid] = v;
    __syncthreads();
    for (int off = 1; off < 1024; off <<= 1) {
        int t = (tid >= off) ? sm[tid - off] : 0;
        __syncthreads();
        sm[tid] += t;
        __syncthreads();
    }
    if (i < NN) g_off[i] = sm[tid] - v;
    if (tid == 1023) g_bsum[blockIdx.x] = sm[1023];
}

// fused scan2+scan3: every block redundantly scans the 98 block sums
__global__ void scan23_kernel(int E) {
    __shared__ int sm[128];
    int tid = threadIdx.x;
    if (tid < 128) sm[tid] = (tid < NB) ? g_bsum[tid] : 0;
    __syncthreads();
    for (int off = 1; off < 128; off <<= 1) {
        int t = (tid < 128 && tid >= off) ? sm[tid - off] : 0;
        __syncthreads();
        if (tid < 128) sm[tid] += t;          // inclusive scan
        __syncthreads();
    }
    int i = blockIdx.x * blockDim.x + tid;
    if (i < NN) {
        int b = i >> 10;
        g_off[i] = g_off[i] + (b ? sm[b - 1] : 0);
    }
    if (i == 0) g_off[NN] = E;
}

// atomic-free fill: position = off[dst] + rank (rank recorded in hist)
__global__ void fill_kernel(const int* __restrict__ src,
                            const int* __restrict__ dst, int E) {
    int e = blockIdx.x * blockDim.x + threadIdx.x;
    if (e >= E) return;
    int p = g_off[dst[e]] + g_rank[e];
    g_ssrc[p] = src[e];
}

// ===========================================================================
// agg1: warp per dst, gather interleaved fp16 x rows, write MEAN (interleaved
// fp16). Elementwise sum is permutation-invariant, so interleave flows through.
// ===========================================================================
__global__ void __launch_bounds__(256) agg1_kernel() {
    int w = (blockIdx.x * 256 + threadIdx.x) >> 5;
    if (w >= NN) return;
    int lane = threadIdx.x & 31;
    int beg = g_off[w], end = g_off[w + 1];
    float a0 = 0.f, a1 = 0.f, a2 = 0.f, a3 = 0.f;
    const uint2* xh = (const uint2*)g_xh;
    int e = beg;
    for (; e + 4 <= end; e += 4) {
        uint2 v0 = __ldg(xh + (long long)__ldg(g_ssrc + e)     * 32 + lane);
        uint2 v1 = __ldg(xh + (long long)__ldg(g_ssrc + e + 1) * 32 + lane);
        uint2 v2 = __ldg(xh + (long long)__ldg(g_ssrc + e + 2) * 32 + lane);
        uint2 v3 = __ldg(xh + (long long)__ldg(g_ssrc + e + 3) * 32 + lane);
        float2 f;
        f = __half22float2(*(__half2*)&v0.x); a0 += f.x; a1 += f.y;
        f = __half22float2(*(__half2*)&v0.y); a2 += f.x; a3 += f.y;
        f = __half22float2(*(__half2*)&v1.x); a0 += f.x; a1 += f.y;
        f = __half22float2(*(__half2*)&v1.y); a2 += f.x; a3 += f.y;
        f = __half22float2(*(__half2*)&v2.x); a0 += f.x; a1 += f.y;
        f = __half22float2(*(__half2*)&v2.y); a2 += f.x; a3 += f.y;
        f = __half22float2(*(__half2*)&v3.x); a0 += f.x; a1 += f.y;
        f = __half22float2(*(__half2*)&v3.y); a2 += f.x; a3 += f.y;
    }
    for (; e < end; e++) {
        uint2 v0 = __ldg(xh + (long long)__ldg(g_ssrc + e) * 32 + lane);
        float2 f;
        f = __half22float2(*(__half2*)&v0.x); a0 += f.x; a1 += f.y;
        f = __half22float2(*(__half2*)&v0.y); a2 += f.x; a3 += f.y;
    }
    float inv = 1.f / (float)max(end - beg, 1);
    uint2 o = make_uint2(h2u(a0 * inv, a1 * inv), h2u(a2 * inv, a3 * inv));
    ((uint2*)g_ag1)[w * 32 + lane] = o;
}

// ===========================================================================
// agg2 + epilogue fused: out[d] = mean_agg(y2l fp16) + b2l + y2r[d]
// ===========================================================================
__global__ void __launch_bounds__(256) agg2_kernel(const float* __restrict__ b2l,
                                                   float* __restrict__ out) {
    int w = (blockIdx.x * 256 + threadIdx.x) >> 5;
    if (w >= NN) return;
    int lane = threadIdx.x & 31;
    int beg = g_off[w], end = g_off[w + 1];
    float ax = 0.f, ay = 0.f;
    const uint* yl = (const uint*)g_y2l;
    int e = beg;
    for (; e + 4 <= end; e += 4) {
        uint v0 = __ldg(yl + (long long)__ldg(g_ssrc + e)     * 32 + lane);
        uint v1 = __ldg(yl + (long long)__ldg(g_ssrc + e + 1) * 32 + lane);
        uint v2 = __ldg(yl + (long long)__ldg(g_ssrc + e + 2) * 32 + lane);
        uint v3 = __ldg(yl + (long long)__ldg(g_ssrc + e + 3) * 32 + lane);
        float2 f;
        f = __half22float2(*(__half2*)&v0); ax += f.x; ay += f.y;
        f = __half22float2(*(__half2*)&v1); ax += f.x; ay += f.y;
        f = __half22float2(*(__half2*)&v2); ax += f.x; ay += f.y;
        f = __half22float2(*(__half2*)&v3); ax += f.x; ay += f.y;
    }
    for (; e < end; e++) {
        uint v0 = __ldg(yl + (long long)__ldg(g_ssrc + e) * 32 + lane);
        float2 f = __half22float2(*(__half2*)&v0);
        ax += f.x; ay += f.y;
    }
    float inv = 1.f / (float)max(end - beg, 1);
    int j = lane * 2;
    float2 yr = *(const float2*)(g_y2r + (long long)w * 64 + j);
    float2 o = make_float2(ax * inv + __ldg(b2l + j)     + yr.x,
                           ay * inv + __ldg(b2l + j + 1) + yr.y);
    *(float2*)(out + (long long)w * 64 + j) = o;
}

// ===========================================================================
// fp16 HMMA GEMMs. Block tile 128x128, 8 warps, warp tile 32x64, k-chunk 128.
// smem: 128 rows x GSTRIDE uints; per row 8 k16-groups x 8 uints (interleaved).
// Fragment loads are single LDS.64 at (row*GSTRIDE + g*8 + 2*cc).
// ===========================================================================
#define TILE_U (128 * GSTRIDE)
#define GEMM1_SMEM ((2 * TILE_U + 256) * 4)
#define GEMM2_SMEM ((2 * TILE_U) * 4)

// straight copy of a pre-interleaved fp16 tile (row-major, 64 uints/row)
__device__ __forceinline__ void copy_tile(uint* S, const uint* __restrict__ src,
                                          int g0, int tid) {
    #pragma unroll
    for (int it = 0; it < 8; it++) {
        int u = it * 256 + tid;
        int r = u >> 4, j = u & 15;
        int grow = g0 + r;
        uint4 v = make_uint4(0u, 0u, 0u, 0u);
        if (grow < NN) v = __ldg((const uint4*)(src + grow * 64) + j);
        *(uint4*)(S + r * GSTRIDE + j * 4) = v;
    }
}

// fp32 weight [128][128] -> interleaved fp16 tile, optional per-row scale
__device__ __forceinline__ void convw_tile(uint* S, const float* __restrict__ W0,
                                           const float* gp, int tid) {
    #pragma unroll
    for (int it = 0; it < 8; it++) {
        int u = it * 256 + tid;
        int n = u >> 4, g = (u >> 1) & 7, h = u & 1;
        const float* p = W0 + n * 128 + g * 16 + 4 * h;
        float4 A = __ldg((const float4*)p);        // k base+0..3
        float4 B = __ldg((const float4*)(p + 8));  // k base+8..11
        float s = gp ? gp[n] : 1.f;
        uint4 o = make_uint4(h2u(A.x * s, A.y * s), h2u(B.x * s, B.y * s),
                             h2u(A.z * s, A.w * s), h2u(B.z * s, B.w * s));
        *(uint4*)(S + n * GSTRIDE + g * 8 + 4 * h) = o;
    }
}

struct FAcc { float a[2][8][4]; };

__device__ __forceinline__ void mainloop_h(const uint* As, const uint* Ws,
                                           int warpM, int warpN, int fr, int cc,
                                           FAcc& acc) {
    const uint* Ab = As + (warpM * 32 + fr) * GSTRIDE + 2 * cc;
    const uint* Bb = Ws + (warpN * 64 + fr) * GSTRIDE + 2 * cc;
    #pragma unroll
    for (int g = 0; g < 8; g++) {
        uint a[2][4];
        #pragma unroll
        for (int mt = 0; mt < 2; mt++) {
            uint2 p0 = *(const uint2*)(Ab + (mt * 16) * GSTRIDE + g * 8);
            uint2 p1 = *(const uint2*)(Ab + (mt * 16 + 8) * GSTRIDE + g * 8);
            a[mt][0] = p0.x; a[mt][1] = p1.x; a[mt][2] = p0.y; a[mt][3] = p1.y;
        }
        #pragma unroll
        for (int nt = 0; nt < 8; nt++) {
            uint2 q = *(const uint2*)(Bb + (nt * 8) * GSTRIDE + g * 8);
            uint b[2] = {q.x, q.y};
            mma16(acc.a[0][nt], a[0], b);
            mma16(acc.a[1][nt], a[1], b);
        }
    }
}

__global__ void __launch_bounds__(256, 2) gemm1_kernel(
    const float* __restrict__ W1l, const float* __restrict__ b1l,
    const float* __restrict__ W1r,
    const float* __restrict__ gamma, const float* __restrict__ beta,
    const float* __restrict__ rmean, const float* __restrict__ rvar)
{
    extern __shared__ uint smu[];
    uint* As = smu;
    uint* Ws = smu + TILE_U;
    float* gp   = (float*)(smu + 2 * TILE_U);
    float* bias = gp + 128;

    int tid = threadIdx.x;
    int g0 = blockIdx.x * 128;

    if (tid < 128) {
        float g = gamma[tid] * rsqrtf(rvar[tid] + EPS);
        gp[tid] = g;
        bias[tid] = (b1l[tid] - rmean[tid]) * g + beta[tid];
    }
    __syncthreads();

    int lane = tid & 31, wid = tid >> 5;
    int warpM = wid >> 1, warpN = wid & 1;
    int fr = lane >> 2, cc = lane & 3;

    FAcc acc;
    #pragma unroll
    for (int i = 0; i < 2; i++)
        #pragma unroll
        for (int j = 0; j < 8; j++)
            #pragma unroll
            for (int q = 0; q < 4; q++) acc.a[i][j][q] = 0.f;

    // chunk 0: mean-agg @ (W1l * gp)^T ; chunk 1: x @ (W1r * gp)^T
    #pragma unroll
    for (int ch = 0; ch < 2; ch++) {
        convw_tile(Ws, ch ? W1r : W1l, gp, tid);
        copy_tile(As, ch ? g_xh : g_ag1, g0, tid);
        __syncthreads();
        mainloop_h(As, Ws, warpM, warpN, fr, cc, acc);
        __syncthreads();
    }

    // epilogue: + bias, ReLU, store interleaved fp16 g_h
    #pragma unroll
    for (int mt = 0; mt < 2; mt++) {
        int r0 = g0 + warpM * 32 + mt * 16 + fr;
        #pragma unroll
        for (int nt = 0; nt < 8; nt++) {
            int col = warpN * 64 + nt * 8 + 2 * cc;     // even
            int t4 = (col & 15) >> 1;
            int j = (t4 < 4) ? 2 * t4 : 2 * (t4 - 4) + 1;
            int uidx = (col >> 4) * 8 + j;
            float b0 = bias[col], b1 = bias[col + 1];
            if (r0 < NN)
                g_h[r0 * 64 + uidx] = h2u(fmaxf(acc.a[mt][nt][0] + b0, 0.f),
                                          fmaxf(acc.a[mt][nt][1] + b1, 0.f));
            if (r0 + 8 < NN)
                g_h[(r0 + 8) * 64 + uidx] = h2u(fmaxf(acc.a[mt][nt][2] + b0, 0.f),
                                                fmaxf(acc.a[mt][nt][3] + b1, 0.f));
        }
    }
}

__global__ void __launch_bounds__(256, 2) gemm2_kernel(
    const float* __restrict__ W2l, const float* __restrict__ W2r)
{
    extern __shared__ uint smu[];
    uint* As = smu;
    uint* Ws = smu + TILE_U;

    int tid = threadIdx.x;
    int g0 = blockIdx.x * 128;

    int lane = tid & 31, wid = tid >> 5;
    int warpM = wid >> 1, warpN = wid & 1;
    int fr = lane >> 2, cc = lane & 3;

    // W tile: n 0..63 -> W2l, 64..127 -> W2r (no scale)
    #pragma unroll
    for (int it = 0; it < 8; it++) {
        int u = it * 256 + tid;
        int n = u >> 4, g = (u >> 1) & 7, h = u & 1;
        const float* Wsrc = (n < 64) ? (W2l + n * 128) : (W2r + (n - 64) * 128);
        const float* p = Wsrc + g * 16 + 4 * h;
        float4 A = __ldg((const float4*)p);
        float4 B = __ldg((const float4*)(p + 8));
        uint4 o = make_uint4(h2u(A.x, A.y), h2u(B.x, B.y),
                             h2u(A.z, A.w), h2u(B.z, B.w));
        *(uint4*)(Ws + n * GSTRIDE + g * 8 + 4 * h) = o;
    }
    copy_tile(As, g_h, g0, tid);
    __syncthreads();

    FAcc acc;
    #pragma unroll
    for (int i = 0; i < 2; i++)
        #pragma unroll
        for (int j = 0; j < 8; j++)
            #pragma unroll
            for (int q = 0; q < 4; q++) acc.a[i][j][q] = 0.f;

    mainloop_h(As, Ws, warpM, warpN, fr, cc, acc);

    // epilogue: warpN==0 -> y2l fp16 plain; warpN==1 -> y2r fp32 plain
    #pragma unroll
    for (int mt = 0; mt < 2; mt++) {
        int r0 = g0 + warpM * 32 + mt * 16 + fr;
        #pragma unroll
        for (int nt = 0; nt < 8; nt++) {
            int colL = nt * 8 + 2 * cc;
            if (warpN == 0) {
                if (r0 < NN)
                    *(__half2*)(g_y2l + (long long)r0 * 64 + colL) =
                        __floats2half2_rn(acc.a[mt][nt][0], acc.a[mt][nt][1]);
                if (r0 + 8 < NN)
                    *(__half2*)(g_y2l + (long long)(r0 + 8) * 64 + colL) =
                        __floats2half2_rn(acc.a[mt][nt][2], acc.a[mt][nt][3]);
            } else {
                if (r0 < NN)
                    *(float2*)(g_y2r + (long long)r0 * 64 + colL) =
                        make_float2(acc.a[mt][nt][0], acc.a[mt][nt][1]);
                if (r0 + 8 < NN)
                    *(float2*)(g_y2r + (long long)(r0 + 8) * 64 + colL) =
                        make_float2(acc.a[mt][nt][2], acc.a[mt][nt][3]);
            }
        }
    }
}

// ===========================================================================
extern "C" void kernel_launch(void* const* d_in, const int* in_sizes, int n_in,
                              void* d_out, int out_size) {
    const float* x     = (const float*)d_in[0];
    const int*   ei    = (const int*)d_in[1];     // int32 (JAX x64 disabled)
    const float* W1l   = (const float*)d_in[2];
    const float* b1l   = (const float*)d_in[3];
    const float* W1r   = (const float*)d_in[4];
    const float* gamma = (const float*)d_in[5];
    const float* beta  = (const float*)d_in[6];
    const float* rmean = (const float*)d_in[7];
    const float* rvar  = (const float*)d_in[8];
    const float* W2l   = (const float*)d_in[9];
    const float* b2l   = (const float*)d_in[10];
    const float* W2r   = (const float*)d_in[11];
    float* out = (float*)d_out;

    int E = in_sizes[1] / 2;
    if (E > EMAX) E = EMAX;
    const int* src = ei;
    const int* dst = ei + E;

    cudaFuncSetAttribute(gemm1_kernel, cudaFuncAttributeMaxDynamicSharedMemorySize, GEMM1_SMEM);
    cudaFuncSetAttribute(gemm2_kernel, cudaFuncAttributeMaxDynamicSharedMemorySize, GEMM2_SMEM);

    int zcBlk = (NN * 8 + 255) / 256;     // 3125
    int eBlk  = (E + 255) / 256;          // 6250
    int nBlk  = (NN + 255) / 256;         // 391
    int wBlk  = (NN * 32 + 255) / 256;    // 12500
    int gBlk  = (NN + 127) / 128;         // 782

    // CSR build + fp16 interleaved staging
    zeroconv_kernel<<<zcBlk, 256>>>(x);
    hist_kernel<<<eBlk, 256>>>(dst, E);
    scan1_kernel<<<NB, 1024>>>();
    scan23_kernel<<<nBlk, 256>>>(E);
    fill_kernel<<<eBlk, 256>>>(src, dst, E);

    // pipeline
    agg1_kernel<<<wBlk, 256>>>();
    gemm1_kernel<<<gBlk, 256, GEMM1_SMEM>>>(W1l, b1l, W1r, gamma, beta, rmean, rvar);
    gemm2_kernel<<<gBlk, 256, GEMM2_SMEM>>>(W2l, W2r);
    agg2_kernel<<<wBlk, 256>>>(b2l, out);
}

// round 16
// speedup vs baseline: 1.0626x; 1.0331x over previous
#include <cuda_runtime.h>
#include <cuda_fp16.h>

#define NN 100000
#define EMAX 1600000
#define EPS 1e-5f
#define NB ((NN + 1023) >> 10)     // 98 scan blocks
#define GSTRIDE 88                 // smem row stride (uints): conflict-free LDS.64/STS.128

typedef unsigned int uint;

// ---- scratch (device globals) ----
// interleaved fp16 layout: per row 128 k-values = 8 groups x 8 uints (half2 each),
// group order [k01,k89,k23,k10-11,k45,k12-13,k67,k14-15]
__device__ __align__(256) uint   g_xh [NN * 64];   // x, fp16 interleaved
__device__ __align__(256) uint   g_ag1[NN * 64];   // mean-agg(x), fp16 interleaved
__device__ __align__(256) uint   g_h  [NN * 64];   // layer-1 out, fp16 interleaved
__device__ __align__(256) __half g_y2l[NN * 64];   // h@W2l^T, fp16 plain
__device__ __align__(256) float  g_y2r[NN * 64];   // h@W2r^T, fp32 plain
__device__ __align__(16) uint g_w1lS[128 * 64];    // (W1l*gp) fp16 interleaved, staged once
__device__ __align__(16) uint g_w1rS[128 * 64];    // (W1r*gp) staged
__device__ __align__(16) uint g_w2S [128 * 64];    // [W2l;W2r] staged
__device__ int g_cnt_i[NN];
__device__ int g_off[NN + 1];
__device__ int g_bsum[NB];
__device__ int g_rank[EMAX];    // edge's rank within its dst bucket (from hist)
__device__ int g_ssrc[EMAX];

// ---- helpers ----
__device__ __forceinline__ uint h2u(float lo, float hi) {
    __half2 h = __floats2half2_rn(lo, hi);
    return *(uint*)&h;
}
__device__ __forceinline__ void mma16(float* d, const uint* a, const uint* b) {
    asm("mma.sync.aligned.m16n8k16.row.col.f32.f16.f16.f32 "
        "{%0,%1,%2,%3}, {%4,%5,%6,%7}, {%8,%9}, {%0,%1,%2,%3};"
        : "+f"(d[0]), "+f"(d[1]), "+f"(d[2]), "+f"(d[3])
        : "r"(a[0]), "r"(a[1]), "r"(a[2]), "r"(a[3]), "r"(b[0]), "r"(b[1]));
}

// ===========================================================================
// prep: zero hist counters + stage all weights as interleaved fp16 (once)
// ===========================================================================
__global__ void prep_kernel(const float* __restrict__ W1l, const float* __restrict__ W1r,
                            const float* __restrict__ W2l, const float* __restrict__ W2r,
                            const float* __restrict__ gamma, const float* __restrict__ rvar) {
    int t = blockIdx.x * 256 + threadIdx.x;
    if (t < NN) g_cnt_i[t] = 0;
    if (t >= 6144) return;                 // 3 tiles x 2048 uint4 items
    int wsel = t >> 11;
    int item = t & 2047;
    int n = item >> 4, j = item & 15;
    int g = j >> 1, h = j & 1;
    const float* Wsrc;
    uint* Wdst;
    float s = 1.f;
    if (wsel == 0) {
        Wsrc = W1l + n * 128; Wdst = g_w1lS;
        s = __ldg(gamma + n) * rsqrtf(__ldg(rvar + n) + EPS);
    } else if (wsel == 1) {
        Wsrc = W1r + n * 128; Wdst = g_w1rS;
        s = __ldg(gamma + n) * rsqrtf(__ldg(rvar + n) + EPS);
    } else {
        Wsrc = (n < 64) ? (W2l + n * 128) : (W2r + (n - 64) * 128);
        Wdst = g_w2S;
    }
    const float* p = Wsrc + g * 16 + 4 * h;
    float4 A = __ldg((const float4*)p);        // k base+0..3
    float4 B = __ldg((const float4*)(p + 8));  // k base+8..11
    uint4 o = make_uint4(h2u(A.x * s, A.y * s), h2u(B.x * s, B.y * s),
                         h2u(A.z * s, A.w * s), h2u(B.z * s, B.w * s));
    *(uint4*)(Wdst + n * 64 + j * 4) = o;
}

// convert x -> interleaved fp16 (side stream; independent of CSR chain)
__global__ void convx_kernel(const float* __restrict__ x) {
    int u = blockIdx.x * 256 + threadIdx.x;
    if (u >= NN * 8) return;
    int row = u >> 3, g = u & 7;
    const float4* p = (const float4*)(x + row * 128 + g * 16);
    float4 a = __ldg(p);        // k0-3
    float4 b = __ldg(p + 1);    // k4-7
    float4 c = __ldg(p + 2);    // k8-11
    float4 d = __ldg(p + 3);    // k12-15
    uint4 o0 = make_uint4(h2u(a.x, a.y), h2u(c.x, c.y), h2u(a.z, a.w), h2u(c.z, c.w));
    uint4 o1 = make_uint4(h2u(b.x, b.y), h2u(d.x, d.y), h2u(b.z, b.w), h2u(d.z, d.w));
    uint4* q = (uint4*)(g_xh + row * 64 + g * 8);
    q[0] = o0; q[1] = o1;
}

// ===========================================================================
// CSR build — hist records each edge's bucket rank; fill is atomic-free.
// ===========================================================================
__global__ void hist_kernel(const int* __restrict__ dst, int E) {
    int e = blockIdx.x * blockDim.x + threadIdx.x;
    if (e < E) g_rank[e] = atomicAdd(&g_cnt_i[dst[e]], 1);
}

__global__ void scan1_kernel() {
    __shared__ int sm[1024];
    int tid = threadIdx.x;
    int i = blockIdx.x * 1024 + tid;
    int v = (i < NN) ? g_cnt_i[i] : 0;
    sm[tid] = v;
    __syncthreads();
    for (int off = 1; off < 1024; off <<= 1) {
        int t = (tid >= off) ? sm[tid - off] : 0;
        __syncthreads();
        sm[tid] += t;
        __syncthreads();
    }
    if (i < NN) g_off[i] = sm[tid] - v;
    if (tid == 1023) g_bsum[blockIdx.x] = sm[1023];
}

// fused scan2+scan3: every block redundantly scans the 98 block sums
__global__ void scan23_kernel(int E) {
    __shared__ int sm[128];
    int tid = threadIdx.x;
    if (tid < 128) sm[tid] = (tid < NB) ? g_bsum[tid] : 0;
    __syncthreads();
    for (int off = 1; off < 128; off <<= 1) {
        int t = (tid < 128 && tid >= off) ? sm[tid - off] : 0;
        __syncthreads();
        if (tid < 128) sm[tid] += t;          // inclusive scan
        __syncthreads();
    }
    int i = blockIdx.x * blockDim.x + tid;
    if (i < NN) {
        int b = i >> 10;
        g_off[i] = g_off[i] + (b ? sm[b - 1] : 0);
    }
    if (i == 0) g_off[NN] = E;
}

// atomic-free fill: position = off[dst] + rank (rank recorded in hist)
__global__ void fill_kernel(const int* __restrict__ src,
                            const int* __restrict__ dst, int E) {
    int e = blockIdx.x * blockDim.x + threadIdx.x;
    if (e >= E) return;
    int p = g_off[dst[e]] + g_rank[e];
    g_ssrc[p] = src[e];
}

// ===========================================================================
// agg1: warp per dst, gather interleaved fp16 x rows, write MEAN (interleaved
// fp16). Elementwise sum is permutation-invariant, so interleave flows through.
// ===========================================================================
__global__ void __launch_bounds__(256) agg1_kernel() {
    int w = (blockIdx.x * 256 + threadIdx.x) >> 5;
    if (w >= NN) return;
    int lane = threadIdx.x & 31;
    int beg = g_off[w], end = g_off[w + 1];
    float a0 = 0.f, a1 = 0.f, a2 = 0.f, a3 = 0.f;
    const uint2* xh = (const uint2*)g_xh;
    int e = beg;
    for (; e + 4 <= end; e += 4) {
        uint2 v0 = __ldg(xh + (long long)__ldg(g_ssrc + e)     * 32 + lane);
        uint2 v1 = __ldg(xh + (long long)__ldg(g_ssrc + e + 1) * 32 + lane);
        uint2 v2 = __ldg(xh + (long long)__ldg(g_ssrc + e + 2) * 32 + lane);
        uint2 v3 = __ldg(xh + (long long)__ldg(g_ssrc + e + 3) * 32 + lane);
        float2 f;
        f = __half22float2(*(__half2*)&v0.x); a0 += f.x; a1 += f.y;
        f = __half22float2(*(__half2*)&v0.y); a2 += f.x; a3 += f.y;
        f = __half22float2(*(__half2*)&v1.x); a0 += f.x; a1 += f.y;
        f = __half22float2(*(__half2*)&v1.y); a2 += f.x; a3 += f.y;
        f = __half22float2(*(__half2*)&v2.x); a0 += f.x; a1 += f.y;
        f = __half22float2(*(__half2*)&v2.y); a2 += f.x; a3 += f.y;
        f = __half22float2(*(__half2*)&v3.x); a0 += f.x; a1 += f.y;
        f = __half22float2(*(__half2*)&v3.y); a2 += f.x; a3 += f.y;
    }
    for (; e < end; e++) {
        uint2 v0 = __ldg(xh + (long long)__ldg(g_ssrc + e) * 32 + lane);
        float2 f;
        f = __half22float2(*(__half2*)&v0.x); a0 += f.x; a1 += f.y;
        f = __half22float2(*(__half2*)&v0.y); a2 += f.x; a3 += f.y;
    }
    float inv = 1.f / (float)max(end - beg, 1);
    uint2 o = make_uint2(h2u(a0 * inv, a1 * inv), h2u(a2 * inv, a3 * inv));
    ((uint2*)g_ag1)[w * 32 + lane] = o;
}

// ===========================================================================
// agg2 + epilogue fused: out[d] = mean_agg(y2l fp16) + b2l + y2r[d]
// ===========================================================================
__global__ void __launch_bounds__(256) agg2_kernel(const float* __restrict__ b2l,
                                                   float* __restrict__ out) {
    int w = (blockIdx.x * 256 + threadIdx.x) >> 5;
    if (w >= NN) return;
    int lane = threadIdx.x & 31;
    int beg = g_off[w], end = g_off[w + 1];
    float ax = 0.f, ay = 0.f;
    const uint* yl = (const uint*)g_y2l;
    int e = beg;
    for (; e + 4 <= end; e += 4) {
        uint v0 = __ldg(yl + (long long)__ldg(g_ssrc + e)     * 32 + lane);
        uint v1 = __ldg(yl + (long long)__ldg(g_ssrc + e + 1) * 32 + lane);
        uint v2 = __ldg(yl + (long long)__ldg(g_ssrc + e + 2) * 32 + lane);
        uint v3 = __ldg(yl + (long long)__ldg(g_ssrc + e + 3) * 32 + lane);
        float2 f;
        f = __half22float2(*(__half2*)&v0); ax += f.x; ay += f.y;
        f = __half22float2(*(__half2*)&v1); ax += f.x; ay += f.y;
        f = __half22float2(*(__half2*)&v2); ax += f.x; ay += f.y;
        f = __half22float2(*(__half2*)&v3); ax += f.x; ay += f.y;
    }
    for (; e < end; e++) {
        uint v0 = __ldg(yl + (long long)__ldg(g_ssrc + e) * 32 + lane);
        float2 f = __half22float2(*(__half2*)&v0);
        ax += f.x; ay += f.y;
    }
    float inv = 1.f / (float)max(end - beg, 1);
    int j = lane * 2;
    float2 yr = *(const float2*)(g_y2r + (long long)w * 64 + j);
    float2 o = make_float2(ax * inv + __ldg(b2l + j)     + yr.x,
                           ay * inv + __ldg(b2l + j + 1) + yr.y);
    *(float2*)(out + (long long)w * 64 + j) = o;
}

// ===========================================================================
// fp16 HMMA GEMMs. Block tile 128x128, 8 warps, warp tile 32x64, k-chunk 128.
// smem: 128 rows x GSTRIDE uints; per row 8 k16-groups x 8 uints (interleaved).
// Fragment loads are single LDS.64 at (row*GSTRIDE + g*8 + 2*cc).
// Weights come pre-staged (interleaved fp16) -> W load is the same copy as A.
// ===========================================================================
#define TILE_U (128 * GSTRIDE)
#define GEMM1_SMEM ((2 * TILE_U + 128) * 4)
#define GEMM2_SMEM ((2 * TILE_U) * 4)

// straight copy of a pre-interleaved fp16 tile (row-major, 64 uints/row)
__device__ __forceinline__ void copy_tile(uint* S, const uint* __restrict__ src,
                                          int g0, int tid) {
    #pragma unroll
    for (int it = 0; it < 8; it++) {
        int u = it * 256 + tid;
        int r = u >> 4, j = u & 15;
        int grow = g0 + r;
        uint4 v = make_uint4(0u, 0u, 0u, 0u);
        if (grow < NN) v = __ldg((const uint4*)(src + grow * 64) + j);
        *(uint4*)(S + r * GSTRIDE + j * 4) = v;
    }
}

struct FAcc { float a[2][8][4]; };

__device__ __forceinline__ void mainloop_h(const uint* As, const uint* Ws,
                                           int warpM, int warpN, int fr, int cc,
                                           FAcc& acc) {
    const uint* Ab = As + (warpM * 32 + fr) * GSTRIDE + 2 * cc;
    const uint* Bb = Ws + (warpN * 64 + fr) * GSTRIDE + 2 * cc;
    #pragma unroll
    for (int g = 0; g < 8; g++) {
        uint a[2][4];
        #pragma unroll
        for (int mt = 0; mt < 2; mt++) {
            uint2 p0 = *(const uint2*)(Ab + (mt * 16) * GSTRIDE + g * 8);
            uint2 p1 = *(const uint2*)(Ab + (mt * 16 + 8) * GSTRIDE + g * 8);
            a[mt][0] = p0.x; a[mt][1] = p1.x; a[mt][2] = p0.y; a[mt][3] = p1.y;
        }
        #pragma unroll
        for (int nt = 0; nt < 8; nt++) {
            uint2 q = *(const uint2*)(Bb + (nt * 8) * GSTRIDE + g * 8);
            uint b[2] = {q.x, q.y};
            mma16(acc.a[0][nt], a[0], b);
            mma16(acc.a[1][nt], a[1], b);
        }
    }
}

__global__ void __launch_bounds__(256, 2) gemm1_kernel(
    const float* __restrict__ b1l,
    const float* __restrict__ gamma, const float* __restrict__ beta,
    const float* __restrict__ rmean, const float* __restrict__ rvar)
{
    extern __shared__ uint smu[];
    uint* As = smu;
    uint* Ws = smu + TILE_U;
    float* bias = (float*)(smu + 2 * TILE_U);

    int tid = threadIdx.x;
    int g0 = blockIdx.x * 128;

    if (tid < 128) {
        float g = gamma[tid] * rsqrtf(rvar[tid] + EPS);
        bias[tid] = (b1l[tid] - rmean[tid]) * g + beta[tid];
    }

    int lane = tid & 31, wid = tid >> 5;
    int warpM = wid >> 1, warpN = wid & 1;
    int fr = lane >> 2, cc = lane & 3;

    FAcc acc;
    #pragma unroll
    for (int i = 0; i < 2; i++)
        #pragma unroll
        for (int j = 0; j < 8; j++)
            #pragma unroll
            for (int q = 0; q < 4; q++) acc.a[i][j][q] = 0.f;

    // chunk 0: mean-agg @ (W1l * gp)^T ; chunk 1: x @ (W1r * gp)^T
    #pragma unroll
    for (int ch = 0; ch < 2; ch++) {
        copy_tile(Ws, ch ? g_w1rS : g_w1lS, 0, tid);
        copy_tile(As, ch ? g_xh : g_ag1, g0, tid);
        __syncthreads();
        mainloop_h(As, Ws, warpM, warpN, fr, cc, acc);
        __syncthreads();
    }

    // epilogue: + bias, ReLU, store interleaved fp16 g_h
    #pragma unroll
    for (int mt = 0; mt < 2; mt++) {
        int r0 = g0 + warpM * 32 + mt * 16 + fr;
        #pragma unroll
        for (int nt = 0; nt < 8; nt++) {
            int col = warpN * 64 + nt * 8 + 2 * cc;     // even
            int t4 = (col & 15) >> 1;
            int j = (t4 < 4) ? 2 * t4 : 2 * (t4 - 4) + 1;
            int uidx = (col >> 4) * 8 + j;
            float b0 = bias[col], b1 = bias[col + 1];
            if (r0 < NN)
                g_h[r0 * 64 + uidx] = h2u(fmaxf(acc.a[mt][nt][0] + b0, 0.f),
                                          fmaxf(acc.a[mt][nt][1] + b1, 0.f));
            if (r0 + 8 < NN)
                g_h[(r0 + 8) * 64 + uidx] = h2u(fmaxf(acc.a[mt][nt][2] + b0, 0.f),
                                                fmaxf(acc.a[mt][nt][3] + b1, 0.f));
        }
    }
}

__global__ void __launch_bounds__(256, 2) gemm2_kernel() {
    extern __shared__ uint smu[];
    uint* As = smu;
    uint* Ws = smu + TILE_U;

    int tid = threadIdx.x;
    int g0 = blockIdx.x * 128;

    int lane = tid & 31, wid = tid >> 5;
    int warpM = wid >> 1, warpN = wid & 1;
    int fr = lane >> 2, cc = lane & 3;

    copy_tile(Ws, g_w2S, 0, tid);
    copy_tile(As, g_h, g0, tid);
    __syncthreads();

    FAcc acc;
    #pragma unroll
    for (int i = 0; i < 2; i++)
        #pragma unroll
        for (int j = 0; j < 8; j++)
            #pragma unroll
            for (int q = 0; q < 4; q++) acc.a[i][j][q] = 0.f;

    mainloop_h(As, Ws, warpM, warpN, fr, cc, acc);

    // epilogue: warpN==0 -> y2l fp16 plain; warpN==1 -> y2r fp32 plain
    #pragma unroll
    for (int mt = 0; mt < 2; mt++) {
        int r0 = g0 + warpM * 32 + mt * 16 + fr;
        #pragma unroll
        for (int nt = 0; nt < 8; nt++) {
            int colL = nt * 8 + 2 * cc;
            if (warpN == 0) {
                if (r0 < NN)
                    *(__half2*)(g_y2l + (long long)r0 * 64 + colL) =
                        __floats2half2_rn(acc.a[mt][nt][0], acc.a[mt][nt][1]);
                if (r0 + 8 < NN)
                    *(__half2*)(g_y2l + (long long)(r0 + 8) * 64 + colL) =
                        __floats2half2_rn(acc.a[mt][nt][2], acc.a[mt][nt][3]);
            } else {
                if (r0 < NN)
                    *(float2*)(g_y2r + (long long)r0 * 64 + colL) =
                        make_float2(acc.a[mt][nt][0], acc.a[mt][nt][1]);
                if (r0 + 8 < NN)
                    *(float2*)(g_y2r + (long long)(r0 + 8) * 64 + colL) =
                        make_float2(acc.a[mt][nt][2], acc.a[mt][nt][3]);
            }
        }
    }
}

// ===========================================================================
extern "C" void kernel_launch(void* const* d_in, const int* in_sizes, int n_in,
                              void* d_out, int out_size) {
    const float* x     = (const float*)d_in[0];
    const int*   ei    = (const int*)d_in[1];     // int32 (JAX x64 disabled)
    const float* W1l   = (const float*)d_in[2];
    const float* b1l   = (const float*)d_in[3];
    const float* W1r   = (const float*)d_in[4];
    const float* gamma = (const float*)d_in[5];
    const float* beta  = (const float*)d_in[6];
    const float* rmean = (const float*)d_in[7];
    const float* rvar  = (const float*)d_in[8];
    const float* W2l   = (const float*)d_in[9];
    const float* b2l   = (const float*)d_in[10];
    const float* W2r   = (const float*)d_in[11];
    float* out = (float*)d_out;

    int E = in_sizes[1] / 2;
    if (E > EMAX) E = EMAX;
    const int* src = ei;
    const int* dst = ei + E;

    cudaFuncSetAttribute(gemm1_kernel, cudaFuncAttributeMaxDynamicSharedMemorySize, GEMM1_SMEM);
    cudaFuncSetAttribute(gemm2_kernel, cudaFuncAttributeMaxDynamicSharedMemorySize, GEMM2_SMEM);

    int cBlk = (NN * 8 + 255) / 256;      // 3125
    int eBlk = (E + 255) / 256;           // 6250
    int nBlk = (NN + 255) / 256;          // 391
    int wBlk = (NN * 32 + 255) / 256;     // 12500
    int gBlk = (NN + 127) / 128;          // 782

    // side stream + events (capture-safe fork, proven R8-R15)
    cudaStream_t s2;
    cudaStreamCreateWithFlags(&s2, cudaStreamNonBlocking);
    cudaEvent_t e0, e1;
    cudaEventCreateWithFlags(&e0, cudaEventDisableTiming);
    cudaEventCreateWithFlags(&e1, cudaEventDisableTiming);

    cudaEventRecord(e0, 0);
    cudaStreamWaitEvent(s2, e0, 0);

    // stream B: x -> interleaved fp16 (overlaps the atomic-bound CSR chain)
    convx_kernel<<<cBlk, 256, 0, s2>>>(x);
    cudaEventRecord(e1, s2);

    // stream A: zero counters + stage weights, then CSR build
    prep_kernel<<<nBlk, 256>>>(W1l, W1r, W2l, W2r, gamma, rvar);
    hist_kernel<<<eBlk, 256>>>(dst, E);
    scan1_kernel<<<NB, 1024>>>();
    scan23_kernel<<<nBlk, 256>>>(E);
    fill_kernel<<<eBlk, 256>>>(src, dst, E);

    cudaStreamWaitEvent(0, e1, 0);        // agg1 needs g_xh
    agg1_kernel<<<wBlk, 256>>>();
    gemm1_kernel<<<gBlk, 256, GEMM1_SMEM>>>(b1l, gamma, beta, rmean, rvar);
    gemm2_kernel<<<gBlk, 256, GEMM2_SMEM>>>();
    agg2_kernel<<<wBlk, 256>>>(b2l, out);
}